// round 8
// baseline (speedup 1.0000x reference)
#include <cuda_runtime.h>

// GaussianHistogram: hist[b,i,j] = sum_n exp(-pi*(f1-i)^2) * exp(-pi*(f2-j)^2) * mask
// (SIGMA = DELTA/sqrt(2pi) makes the exponent exactly -pi*d^2 and COEF == 1.0.)
//
// L1tex-wavefront model (fit over R3-R6): ~2.26 cyc per RED instruction-lane
// per SM, width-independent -> the scatter runs at its floor of 3 v4-REDs per
// sample via two column-shifted scratch replicas (shift r = (i2-1)&2 makes the
// 3 taps always fit one 16B-aligned window). Epilogue folds the replicas:
//   out[b,i,j] = S0[b,i,j] + S2[b,i,j-2]
// and ZEROES scratch in the same pass (no separate memset node). Scratch is
// zero at module load (BSS) and each execution restores the zero invariant,
// so every call is deterministic.

#define GH_BINS   256
#define GH_LOGN   15          // N = 32768 per batch
#define GH_BATCH  8
#define GH_PLANE  (GH_BINS*GH_BINS)              // 65536
#define GH_TOTALH (GH_BATCH*GH_PLANE)            // 524288

__device__ float gh_scratch[2 * GH_TOTALH];      // 4 MB, zero-invariant

__global__ void __launch_bounds__(256)
gh_scatter_kernel(const float* __restrict__ x1,
                  const float* __restrict__ x2,
                  const float* __restrict__ mask,
                  int total)
{
    int idx = blockIdx.x * blockDim.x + threadIdx.x;
    if (idx >= total) return;

    int b = idx >> GH_LOGN;           // batch index (N = 32768)

    float a1 = x1[idx];
    float a2 = x2[idx];
    float m  = mask[idx];

    // continuous bin coordinate: f = (x - MIN_V)/DELTA - 0.5 ; center c_i sits at f == i
    const float INV_DELTA = 256.0f / 1.5f;
    float f1 = (a1 + 0.25f) * INV_DELTA - 0.5f;
    float f2 = (a2 + 0.25f) * INV_DELTA - 0.5f;

    int i1 = (int)floorf(f1 + 0.5f);  // nearest bin
    int i2 = (int)floorf(f2 + 0.5f);
    // x in [0,1) => i in [42,213]; clamps are pure OOB insurance.
    i1 = min(max(i1, 1), GH_BINS - 2);
    i2 = min(max(i2, 1), GH_BINS - 2);

    float u1 = f1 - (float)i1;        // in [-0.5, 0.5]
    float u2 = f2 - (float)i2;

    const float NPI_L2E = -4.53236014182719f;   // -pi * log2(e)

    // 3 row weights (x1 direction)
    float dm = u1 + 1.0f, dp = u1 - 1.0f;
    float w0 = exp2f(NPI_L2E * dm * dm);
    float w1 = exp2f(NPI_L2E * u1 * u1);
    float w2 = exp2f(NPI_L2E * dp * dp);

    // 3 column taps (x2 direction), mask folded in
    float em = u2 + 1.0f, ep = u2 - 1.0f;
    float t0 = exp2f(NPI_L2E * em * em) * m;
    float t1 = exp2f(NPI_L2E * u2 * u2) * m;
    float t2 = exp2f(NPI_L2E * ep * ep) * m;

    // replica selection: taps at cols a..a+2, a = i2-1 in [0,253].
    // r = a&2 makes (a-r)&3 in {0,1}: taps fit one aligned v4 window.
    int a   = i2 - 1;
    int r   = a & 2;                  // 0 or 2
    int am  = a - r;
    int w   = am & ~3;                // window start in replica, [0,248]
    bool od = (am & 1) != 0;

    float g0 = od ? 0.0f : t0;
    float g1 = od ? t0   : t1;
    float g2 = od ? t1   : t2;
    float g3 = od ? t2   : 0.0f;

    float* base = gh_scratch + (size_t)(r >> 1) * GH_TOTALH
                             + ((size_t)b << 16)
                             + (size_t)(i1 - 1) * GH_BINS
                             + w;

    float p0 = w0*g0, p1 = w0*g1, p2 = w0*g2, p3 = w0*g3;
    asm volatile("red.global.add.v4.f32 [%0], {%1,%2,%3,%4};"
                 :: "l"(base), "f"(p0), "f"(p1), "f"(p2), "f"(p3) : "memory");
    p0 = w1*g0; p1 = w1*g1; p2 = w1*g2; p3 = w1*g3;
    asm volatile("red.global.add.v4.f32 [%0], {%1,%2,%3,%4};"
                 :: "l"(base + GH_BINS), "f"(p0), "f"(p1), "f"(p2), "f"(p3) : "memory");
    p0 = w2*g0; p1 = w2*g1; p2 = w2*g2; p3 = w2*g3;
    asm volatile("red.global.add.v4.f32 [%0], {%1,%2,%3,%4};"
                 :: "l"(base + 2*GH_BINS), "f"(p0), "f"(p1), "f"(p2), "f"(p3) : "memory");
}

// out[b,i,j] = S0[b,i,j] + S2[b,i,j-2], then zero both scratch replicas.
// All accesses are 16B-aligned v4; the S2 "lo" half comes from the previous
// aligned float4 (predicated off at row start j==0, where cols -2/-1 don't
// exist; S2 cols 252-255 are never written by the scatter, so the shifted
// read never picks up a previous row's data).
__global__ void __launch_bounds__(256)
gh_gather_kernel(float* __restrict__ out)
{
    int t = blockIdx.x * blockDim.x + threadIdx.x;   // one float4 of output
    int base = t * 4;
    if (base >= GH_TOTALH) return;

    int j = base & (GH_BINS - 1);                    // column of first element

    float* S0 = gh_scratch;
    float* S2 = gh_scratch + GH_TOTALH;

    float4 v  = *reinterpret_cast<const float4*>(S0 + base);
    float4 b2 = *reinterpret_cast<const float4*>(S2 + base);

    float lo0 = 0.0f, lo1 = 0.0f;
    if (j != 0) {                                    // j >= 4 (multiple of 4)
        float4 a2 = *reinterpret_cast<const float4*>(S2 + base - 4);
        lo0 = a2.z; lo1 = a2.w;
    }

    v.x += lo0;  v.y += lo1;  v.z += b2.x;  v.w += b2.y;

    *reinterpret_cast<float4*>(out + base) = v;

    // restore the zero invariant for the next execution
    float4 z = make_float4(0.f, 0.f, 0.f, 0.f);
    *reinterpret_cast<float4*>(S0 + base) = z;
    *reinterpret_cast<float4*>(S2 + base) = z;
}

extern "C" void kernel_launch(void* const* d_in, const int* in_sizes, int n_in,
                              void* d_out, int out_size)
{
    const float* x1   = (const float*)d_in[0];
    const float* x2   = (const float*)d_in[1];
    const float* mask = (const float*)d_in[2];
    float* out = (float*)d_out;

    int total = in_sizes[0];               // B*N = 262144
    int threads = 256;
    int blocks = (total + threads - 1) / threads;
    gh_scatter_kernel<<<blocks, threads>>>(x1, x2, mask, total);

    int gthreads = 256;
    int gblocks  = (GH_TOTALH / 4 + gthreads - 1) / gthreads;   // 512
    gh_gather_kernel<<<gblocks, gthreads>>>(out);
}

// round 12
// speedup vs baseline: 1.1184x; 1.1184x over previous
#include <cuda_runtime.h>

// GaussianHistogram: hist[b,i,j] = sum_n exp(-pi*(f1-i)^2) * exp(-pi*(f2-j)^2) * mask
// (SIGMA = DELTA/sqrt(2pi) makes the exponent exactly -pi*d^2 and COEF == 1.0.)
//
// Scatter at the L1tex-wavefront floor: 3 coalesced-width v4 REDs per sample.
// The 16B alignment requirement is met by splitting samples between TWO
// column-shifted targets chosen by r = (i2-1)&2:
//   r==0 -> directly into out        (cols as-is)
//   r==2 -> into scratch S2          (cols shifted by -2)
// Epilogue (load-byte-bound at ~2TB/s effective): loads ONLY S2 (2MB), folds
// with red.add.v4 into out (no out loads), and zero-stores S2 to restore the
// zero invariant. out itself is zeroed by a memset node each execution.

#define GH_BINS   256
#define GH_LOGN   15          // N = 32768 per batch
#define GH_BATCH  8
#define GH_PLANE  (GH_BINS*GH_BINS)              // 65536
#define GH_TOTALH (GH_BATCH*GH_PLANE)            // 524288

// 4-float front pad makes the shifted gather read branchless at base==0.
// Pad and per-row cols 252..255 of S2 are never written -> permanently zero.
__device__ float gh_s2[4 + GH_TOTALH];           // ~2 MB, zero-invariant

__global__ void __launch_bounds__(256)
gh_scatter_kernel(const float* __restrict__ x1,
                  const float* __restrict__ x2,
                  const float* __restrict__ mask,
                  float* __restrict__ out,
                  int total)
{
    int idx = blockIdx.x * blockDim.x + threadIdx.x;
    if (idx >= total) return;

    int b = idx >> GH_LOGN;           // batch index (N = 32768)

    float a1 = x1[idx];
    float a2 = x2[idx];
    float m  = mask[idx];

    // continuous bin coordinate: f = (x - MIN_V)/DELTA - 0.5 ; center c_i sits at f == i
    const float INV_DELTA = 256.0f / 1.5f;
    float f1 = (a1 + 0.25f) * INV_DELTA - 0.5f;
    float f2 = (a2 + 0.25f) * INV_DELTA - 0.5f;

    int i1 = (int)floorf(f1 + 0.5f);  // nearest bin
    int i2 = (int)floorf(f2 + 0.5f);
    // x in [0,1) => i in [42,213]; clamps are pure OOB insurance.
    i1 = min(max(i1, 1), GH_BINS - 2);
    i2 = min(max(i2, 1), GH_BINS - 2);

    float u1 = f1 - (float)i1;        // in [-0.5, 0.5]
    float u2 = f2 - (float)i2;

    const float NPI_L2E = -4.53236014182719f;   // -pi * log2(e)

    // 3 row weights (x1 direction)
    float dm = u1 + 1.0f, dp = u1 - 1.0f;
    float w0 = exp2f(NPI_L2E * dm * dm);
    float w1 = exp2f(NPI_L2E * u1 * u1);
    float w2 = exp2f(NPI_L2E * dp * dp);

    // 3 column taps (x2 direction), mask folded in
    float em = u2 + 1.0f, ep = u2 - 1.0f;
    float t0 = exp2f(NPI_L2E * em * em) * m;
    float t1 = exp2f(NPI_L2E * u2 * u2) * m;
    float t2 = exp2f(NPI_L2E * ep * ep) * m;

    // taps at cols a..a+2, a = i2-1 in [0,253].
    // r = a&2: with am = a-r, am&3 in {0,1} -> taps fit one aligned v4 window.
    int a   = i2 - 1;
    int r   = a & 2;                  // 0 -> out, 2 -> S2 replica
    int am  = a - r;
    int w   = am & ~3;                // aligned window start
    bool od = (am & 1) != 0;

    float g0 = od ? 0.0f : t0;
    float g1 = od ? t0   : t1;
    float g2 = od ? t1   : t2;
    float g3 = od ? t2   : 0.0f;

    size_t off = ((size_t)b << 16) + (size_t)(i1 - 1) * GH_BINS + w;
    float* base = (r == 0) ? (out + off) : (gh_s2 + 4 + off);

    float p0 = w0*g0, p1 = w0*g1, p2 = w0*g2, p3 = w0*g3;
    asm volatile("red.global.add.v4.f32 [%0], {%1,%2,%3,%4};"
                 :: "l"(base), "f"(p0), "f"(p1), "f"(p2), "f"(p3) : "memory");
    p0 = w1*g0; p1 = w1*g1; p2 = w1*g2; p3 = w1*g3;
    asm volatile("red.global.add.v4.f32 [%0], {%1,%2,%3,%4};"
                 :: "l"(base + GH_BINS), "f"(p0), "f"(p1), "f"(p2), "f"(p3) : "memory");
    p0 = w2*g0; p1 = w2*g1; p2 = w2*g2; p3 = w2*g3;
    asm volatile("red.global.add.v4.f32 [%0], {%1,%2,%3,%4};"
                 :: "l"(base + 2*GH_BINS), "f"(p0), "f"(p1), "f"(p2), "f"(p3) : "memory");
}

// Fold: out[b,i,j] += S2[b,i,j-2], then zero S2.
// Per thread (one output float4 at element index base = 4t):
//   lo = S2p[base]   (.z,.w = cols j-2,j-1 ; pad/never-written cols make the
//                     unconditional read safe and zero across row boundaries)
//   hi = S2p[base+4] (.x,.y = cols j,j+1)
//   red.add.v4 -> out[base] ; zero-store S2p[base+4].
__global__ void __launch_bounds__(256)
gh_fold_kernel(float* __restrict__ out)
{
    int t = blockIdx.x * blockDim.x + threadIdx.x;
    int base = t * 4;
    if (base >= GH_TOTALH) return;

    float* S2p = gh_s2;                       // pad-origin: data lives at +4

    float4 lo = *reinterpret_cast<const float4*>(S2p + base);
    float4 hi = *reinterpret_cast<const float4*>(S2p + base + 4);

    // skip the RED entirely when this window has no mass (common: S2 is sparse-ish)
    float s = fabsf(lo.z) + fabsf(lo.w) + fabsf(hi.x) + fabsf(hi.y);
    if (s != 0.0f) {
        asm volatile("red.global.add.v4.f32 [%0], {%1,%2,%3,%4};"
                     :: "l"(out + base), "f"(lo.z), "f"(lo.w), "f"(hi.x), "f"(hi.y)
                     : "memory");
    }

    // restore zero invariant for the region this thread owns (data slot base+4)
    *reinterpret_cast<float4*>(S2p + base + 4) = make_float4(0.f, 0.f, 0.f, 0.f);
}

extern "C" void kernel_launch(void* const* d_in, const int* in_sizes, int n_in,
                              void* d_out, int out_size)
{
    const float* x1   = (const float*)d_in[0];
    const float* x2   = (const float*)d_in[1];
    const float* mask = (const float*)d_in[2];
    float* out = (float*)d_out;

    // out accumulates REDs directly -> zero it (memset node; graph-capturable)
    cudaMemsetAsync(d_out, 0, (size_t)out_size * sizeof(float));

    int total = in_sizes[0];               // B*N = 262144
    int threads = 256;
    int blocks = (total + threads - 1) / threads;
    gh_scatter_kernel<<<blocks, threads>>>(x1, x2, mask, out, total);

    int fthreads = 256;
    int fblocks  = (GH_TOTALH / 4 + fthreads - 1) / fthreads;   // 512
    gh_fold_kernel<<<fblocks, fthreads>>>(out);
}